// round 3
// baseline (speedup 1.0000x reference)
#include <cuda_runtime.h>
#include <math.h>

#define CG 128
#define CN 64
#define CS 64
#define KK 27
#define EPS 1e-5f

#define MAX_NG 60000
#define MAX_NX 200000

#define NBLK 296
#define NTHR 256

// -------- scratch (device globals: no allocations allowed) --------
__device__ float d_fg[MAX_NG * CN];
__device__ float d_fs[MAX_NG * CN];
__device__ float d_z[MAX_NG];
__device__ float d_att[MAX_NG];
__device__ float d_S[MAX_NX * KK];
__device__ float d_part[NBLK][256];    // per-block [sumg64|sqg64|sums64|sqs64]
__device__ float d_zpart[NBLK][2];     // per-block [sum_z, sq_z]
__device__ unsigned d_bar_cnt[4];      // zero-init; returns to 0 every use
__device__ unsigned d_bar_gen[4];      // monotonically increasing across launches

// -------- ad-hoc grid barrier (all NBLK blocks are co-resident by construction) ----
__device__ __forceinline__ void grid_sync(int id) {
    __syncthreads();
    if (threadIdx.x == 0) {
        volatile unsigned* genp = (volatile unsigned*)&d_bar_gen[id];
        unsigned gen = *genp;
        __threadfence();
        unsigned t = atomicAdd(&d_bar_cnt[id], 1u);
        if (t == NBLK - 1) {
            d_bar_cnt[id] = 0;
            __threadfence();
            atomicExch((unsigned*)&d_bar_gen[id], gen + 1u);
        } else {
            while (*genp == gen) __nanosleep(64);
            __threadfence();
        }
    }
    __syncthreads();
}

__global__ __launch_bounds__(NTHR, 2) void mega_kernel(
    const float* __restrict__ g, const float* __restrict__ x,
    const int* __restrict__ down_idx,
    const int* __restrict__ pairs_in, const int* __restrict__ pairs_out,
    const float* __restrict__ Wg, const float* __restrict__ Ws,
    const float* __restrict__ Wc, const float* __restrict__ Winv,
    const float* __restrict__ binv,
    const float* __restrict__ gg, const float* __restrict__ bg,
    const float* __restrict__ gs, const float* __restrict__ bs,
    const float* __restrict__ gamma_c, const float* __restrict__ beta_c,
    float* __restrict__ out,
    int Ng, int Nx, int P) {

    extern __shared__ float smem[];          // 48 KB dynamic
    float* smWg = smem;                      // [8192] 32 KB  (phase1)
    float* smWs = smem + CG * CN;            // [4096] 16 KB  (phase1)

    const int t   = threadIdx.x;
    const int b   = blockIdx.x;
    const int gtid = b * NTHR + t;
    const int gstride = NBLK * NTHR;
    const int wid = t >> 5, lane = t & 31;

    // ================= PHASE 0: zero S =================
    {
        int nS = Nx * KK;
        int nS4 = nS >> 2;
        float4* S4 = (float4*)d_S;
        const float4 z4 = make_float4(0.f, 0.f, 0.f, 0.f);
        for (int e = gtid; e < nS4; e += gstride) S4[e] = z4;
        for (int e = (nS4 << 2) + gtid; e < nS; e += gstride) d_S[e] = 0.f;
    }

    // ================= PHASE 1: both GEMMs + register stats =================
    for (int i = t; i < CG * CN; i += NTHR) smWg[i] = Wg[i];
    for (int i = t; i < CS * CN; i += NTHR) smWs[i] = Ws[i];
    __syncthreads();

    const int tr = t >> 3;            // 0..31 row group within tile
    const int c0 = (t & 7) * 8;       // fixed column group for this thread
    const float4 zero4 = make_float4(0.f, 0.f, 0.f, 0.f);

    float csumg[8], csqg[8], csums[8], csqs[8];
#pragma unroll
    for (int i = 0; i < 8; i++) { csumg[i] = csqg[i] = csums[i] = csqs[i] = 0.f; }

    const int ntiles = (Ng + 127) / 128;
    for (int tile = b; tile < ntiles; tile += NBLK) {
        const int r0 = tile * 128 + tr * 4;

        // ---- g branch: fg = g @ Wg ----
        {
            float acc[4][8];
#pragma unroll
            for (int j = 0; j < 4; j++)
#pragma unroll
                for (int i = 0; i < 8; i++) acc[j][i] = 0.f;

            bool v[4];
            const float4* gp[4];
#pragma unroll
            for (int j = 0; j < 4; j++) {
                v[j] = (r0 + j) < Ng;
                gp[j] = (const float4*)(g + (size_t)(r0 + j) * CG);
            }
#pragma unroll 2
            for (int k4 = 0; k4 < CG / 4; k4++) {
                float4 a[4];
#pragma unroll
                for (int j = 0; j < 4; j++) a[j] = v[j] ? __ldg(&gp[j][k4]) : zero4;
#pragma unroll
                for (int kk = 0; kk < 4; kk++) {
                    int k = k4 * 4 + kk;
                    float4 w0 = *(const float4*)&smWg[k * CN + c0];
                    float4 w1 = *(const float4*)&smWg[k * CN + c0 + 4];
#pragma unroll
                    for (int j = 0; j < 4; j++) {
                        float av = (&a[j].x)[kk];
                        acc[j][0] = fmaf(av, w0.x, acc[j][0]);
                        acc[j][1] = fmaf(av, w0.y, acc[j][1]);
                        acc[j][2] = fmaf(av, w0.z, acc[j][2]);
                        acc[j][3] = fmaf(av, w0.w, acc[j][3]);
                        acc[j][4] = fmaf(av, w1.x, acc[j][4]);
                        acc[j][5] = fmaf(av, w1.y, acc[j][5]);
                        acc[j][6] = fmaf(av, w1.z, acc[j][6]);
                        acc[j][7] = fmaf(av, w1.w, acc[j][7]);
                    }
                }
            }
#pragma unroll
            for (int j = 0; j < 4; j++) {
                if (r0 + j < Ng) {
                    float* o = d_fg + (size_t)(r0 + j) * CN + c0;
                    *(float4*)(o)     = make_float4(acc[j][0], acc[j][1], acc[j][2], acc[j][3]);
                    *(float4*)(o + 4) = make_float4(acc[j][4], acc[j][5], acc[j][6], acc[j][7]);
                }
            }
#pragma unroll
            for (int i = 0; i < 8; i++) {
                csumg[i] += acc[0][i] + acc[1][i] + acc[2][i] + acc[3][i];
                csqg[i]  += acc[0][i] * acc[0][i] + acc[1][i] * acc[1][i]
                          + acc[2][i] * acc[2][i] + acc[3][i] * acc[3][i];
            }
        }

        // ---- s branch: fs = x[down_idx] @ Ws ----
        {
            float acc[4][8];
#pragma unroll
            for (int j = 0; j < 4; j++)
#pragma unroll
                for (int i = 0; i < 8; i++) acc[j][i] = 0.f;

            bool v[4];
            const float4* xp[4];
#pragma unroll
            for (int j = 0; j < 4; j++) {
                v[j] = (r0 + j) < Ng;
                int di = v[j] ? __ldg(&down_idx[r0 + j]) : 0;
                xp[j] = (const float4*)(x + (size_t)di * CS);
            }
#pragma unroll 2
            for (int k4 = 0; k4 < CS / 4; k4++) {
                float4 a[4];
#pragma unroll
                for (int j = 0; j < 4; j++) a[j] = v[j] ? __ldg(&xp[j][k4]) : zero4;
#pragma unroll
                for (int kk = 0; kk < 4; kk++) {
                    int k = k4 * 4 + kk;
                    float4 w0 = *(const float4*)&smWs[k * CN + c0];
                    float4 w1 = *(const float4*)&smWs[k * CN + c0 + 4];
#pragma unroll
                    for (int j = 0; j < 4; j++) {
                        float av = (&a[j].x)[kk];
                        acc[j][0] = fmaf(av, w0.x, acc[j][0]);
                        acc[j][1] = fmaf(av, w0.y, acc[j][1]);
                        acc[j][2] = fmaf(av, w0.z, acc[j][2]);
                        acc[j][3] = fmaf(av, w0.w, acc[j][3]);
                        acc[j][4] = fmaf(av, w1.x, acc[j][4]);
                        acc[j][5] = fmaf(av, w1.y, acc[j][5]);
                        acc[j][6] = fmaf(av, w1.z, acc[j][6]);
                        acc[j][7] = fmaf(av, w1.w, acc[j][7]);
                    }
                }
            }
#pragma unroll
            for (int j = 0; j < 4; j++) {
                if (r0 + j < Ng) {
                    float* o = d_fs + (size_t)(r0 + j) * CN + c0;
                    *(float4*)(o)     = make_float4(acc[j][0], acc[j][1], acc[j][2], acc[j][3]);
                    *(float4*)(o + 4) = make_float4(acc[j][4], acc[j][5], acc[j][6], acc[j][7]);
                }
            }
#pragma unroll
            for (int i = 0; i < 8; i++) {
                csums[i] += acc[0][i] + acc[1][i] + acc[2][i] + acc[3][i];
                csqs[i]  += acc[0][i] * acc[0][i] + acc[1][i] * acc[1][i]
                          + acc[2][i] * acc[2][i] + acc[3][i] * acc[3][i];
            }
        }
    }

    // ---- block-level stats reduction -> d_part[b] (reuses Wg/Ws smem) ----
    {
        __syncthreads();
        float* s_sum = smem;           // [32][64]
        float* s_sq  = smem + 2048;    // [32][64]
        const int col = t & 63, seg = t >> 6;

        // g branch
#pragma unroll
        for (int i = 0; i < 8; i++) {
            s_sum[tr * 64 + c0 + i] = csumg[i];
            s_sq[tr * 64 + c0 + i]  = csqg[i];
        }
        __syncthreads();
        float v1 = 0.f, v2 = 0.f;
#pragma unroll
        for (int r = 0; r < 8; r++) {
            v1 += s_sum[(seg * 8 + r) * 64 + col];
            v2 += s_sq[(seg * 8 + r) * 64 + col];
        }
        __syncthreads();
        s_sum[seg * 64 + col] = v1;
        s_sq[seg * 64 + col]  = v2;
        __syncthreads();
        if (t < 64) {
            d_part[b][t]      = s_sum[t] + s_sum[64 + t] + s_sum[128 + t] + s_sum[192 + t];
            d_part[b][64 + t] = s_sq[t]  + s_sq[64 + t]  + s_sq[128 + t]  + s_sq[192 + t];
        }
        __syncthreads();

        // s branch
#pragma unroll
        for (int i = 0; i < 8; i++) {
            s_sum[tr * 64 + c0 + i] = csums[i];
            s_sq[tr * 64 + c0 + i]  = csqs[i];
        }
        __syncthreads();
        v1 = 0.f; v2 = 0.f;
#pragma unroll
        for (int r = 0; r < 8; r++) {
            v1 += s_sum[(seg * 8 + r) * 64 + col];
            v2 += s_sq[(seg * 8 + r) * 64 + col];
        }
        __syncthreads();
        s_sum[seg * 64 + col] = v1;
        s_sq[seg * 64 + col]  = v2;
        __syncthreads();
        if (t < 64) {
            d_part[b][128 + t] = s_sum[t] + s_sum[64 + t] + s_sum[128 + t] + s_sum[192 + t];
            d_part[b][192 + t] = s_sq[t]  + s_sq[64 + t]  + s_sq[128 + t]  + s_sq[192 + t];
        }
    }

    grid_sync(0);

    // ================= PHASE 2: BN fold + fuse -> z, z-stats =================
    float* wc  = smem;          // [64]
    float* sgn = smem + 64;     // [64]
    float* bgn = smem + 128;
    float* ssn = smem + 192;
    float* bsn = smem + 256;
    float* zs  = smem + 320;    // [8][2]

    if (t < 128) {
        const int c = t & 63;
        const int br = t >> 6;  // 0 = gate, 1 = shortcut
        float sum = 0.f, sq = 0.f;
        const int base = br * 128 + c;
#pragma unroll 4
        for (int bb = 0; bb < NBLK; bb++) {
            sum += __ldcg(&d_part[bb][base]);
            sq  += __ldcg(&d_part[bb][base + 64]);
        }
        const float inv = 1.f / (float)Ng;
        float mu = sum * inv;
        float var = sq * inv - mu * mu;
        float gam = br ? __ldg(&gs[c]) : __ldg(&gg[c]);
        float bet = br ? __ldg(&bs[c]) : __ldg(&bg[c]);
        float sc = gam * rsqrtf(var + EPS);
        if (br == 0) { sgn[c] = sc; bgn[c] = bet - mu * sc; wc[c] = __ldg(&Wc[c]); }
        else         { ssn[c] = sc; bsn[c] = bet - mu * sc; }
    }
    __syncthreads();

    {
        float bsum = 0.f, bsq = 0.f;
        for (int row = b * 8 + wid; row < Ng; row += NBLK * 8) {
            const int c = 2 * lane;
            float2 fg2 = *(const float2*)__builtin_assume_aligned(&d_fg[(size_t)row * CN + c], 8);
            float2 fs2 = *(const float2*)__builtin_assume_aligned(&d_fs[(size_t)row * CN + c], 8);
            float h0 = fmaxf(fg2.x * sgn[c] + bgn[c], 0.f) + fmaxf(fs2.x * ssn[c] + bsn[c], 0.f);
            float h1 = fmaxf(fg2.y * sgn[c + 1] + bgn[c + 1], 0.f) + fmaxf(fs2.y * ssn[c + 1] + bsn[c + 1], 0.f);
            float part = h0 * wc[c] + h1 * wc[c + 1];
#pragma unroll
            for (int o = 16; o > 0; o >>= 1) part += __shfl_down_sync(0xffffffffu, part, o);
            if (lane == 0) {
                d_z[row] = part;
                bsum += part;
                bsq += part * part;
            }
        }
        if (lane == 0) { zs[wid * 2] = bsum; zs[wid * 2 + 1] = bsq; }
        __syncthreads();
        if (t == 0) {
            float a = 0.f, q = 0.f;
#pragma unroll
            for (int w = 0; w < 8; w++) { a += zs[w * 2]; q += zs[w * 2 + 1]; }
            d_zpart[b][0] = a;
            d_zpart[b][1] = q;
        }
    }

    grid_sync(1);

    // ================= PHASE 3: att = sigmoid(bn(z)) =================
    {
        float* zred = smem;  // [2]
        if (t < 2) zred[t] = 0.f;
        __syncthreads();
        float a = 0.f, q = 0.f;
        for (int bb = t; bb < NBLK; bb += NTHR) {
            a += __ldcg(&d_zpart[bb][0]);
            q += __ldcg(&d_zpart[bb][1]);
        }
        atomicAdd(&zred[0], a);
        atomicAdd(&zred[1], q);
        __syncthreads();
        const float inv = 1.f / (float)Ng;
        float mu = zred[0] * inv;
        float var = zred[1] * inv - mu * mu;
        float rs = rsqrtf(var + EPS);
        float gc = __ldg(&gamma_c[0]), bc = __ldg(&beta_c[0]);
        for (int i = gtid; i < Ng; i += gstride) {
            float zz = (__ldcg(&d_z[i]) - mu) * rs * gc + bc;
            d_att[i] = 1.f / (1.f + expf(-zz));
        }
    }

    grid_sync(2);

    // ================= PHASE 4: scatter scalars into S[Nx][27] =================
    for (int k = 0; k < KK; k++) {
        const int* pin  = pairs_in + (size_t)k * P;
        const int* pout = pairs_out + (size_t)k * P;
        for (int i = gtid; i < P; i += gstride) {
            float a = __ldg(&d_att[__ldg(&pin[i])]);
            atomicAdd(&d_S[(size_t)__ldg(&pout[i]) * KK + k], a);
        }
    }

    grid_sync(3);

    // ================= PHASE 5: out = x * (S @ W_inv + b_inv) =================
    {
        float* w  = smem;              // [27][64]
        float* bb2 = smem + KK * CN;   // [64]
        for (int i = t; i < KK * CN; i += NTHR) w[i] = Winv[i];
        if (t < CN) bb2[t] = binv[t];
        __syncthreads();

        for (int row = b * 8 + wid; row < Nx; row += NBLK * 8) {
            float sval = (lane < KK) ? __ldcg(&d_S[(size_t)row * KK + lane]) : 0.f;
            const int c = 2 * lane;
            float a0 = bb2[c], a1 = bb2[c + 1];
#pragma unroll
            for (int k = 0; k < KK; k++) {
                float sk = __shfl_sync(0xffffffffu, sval, k);
                a0 = fmaf(sk, w[k * CN + c], a0);
                a1 = fmaf(sk, w[k * CN + c + 1], a1);
            }
            float2 xv = *(const float2*)&x[(size_t)row * CS + c];
            float2 o;
            o.x = xv.x * a0;
            o.y = xv.y * a1;
            *(float2*)&out[(size_t)row * CS + c] = o;
        }
    }
}

extern "C" void kernel_launch(void* const* d_in, const int* in_sizes, int n_in,
                              void* d_out, int out_size) {
    const float* g        = (const float*)d_in[0];
    const float* x        = (const float*)d_in[1];
    const int*   down_idx = (const int*)d_in[2];
    const int*   pairs_in = (const int*)d_in[3];
    const int*   pairs_out= (const int*)d_in[4];
    const float* Wg       = (const float*)d_in[5];
    const float* Ws       = (const float*)d_in[6];
    const float* Wc       = (const float*)d_in[7];
    const float* W_inv    = (const float*)d_in[8];
    const float* b_inv    = (const float*)d_in[9];
    const float* gamma_g  = (const float*)d_in[10];
    const float* beta_g   = (const float*)d_in[11];
    const float* gamma_s  = (const float*)d_in[12];
    const float* beta_s   = (const float*)d_in[13];
    const float* gamma_c  = (const float*)d_in[14];
    const float* beta_c   = (const float*)d_in[15];

    int Ng = in_sizes[0] / CG;
    int Nx = in_sizes[1] / CS;
    int KP = in_sizes[3];
    int P  = KP / KK;

    size_t smem_bytes = 48 * 1024;
    mega_kernel<<<NBLK, NTHR, smem_bytes>>>(
        g, x, down_idx, pairs_in, pairs_out, Wg, Ws, Wc, W_inv, b_inv,
        gamma_g, beta_g, gamma_s, beta_s, gamma_c, beta_c,
        (float*)d_out, Ng, Nx, P);
}

// round 4
// speedup vs baseline: 1.3650x; 1.3650x over previous
#include <cuda_runtime.h>
#include <cuda_fp16.h>
#include <math.h>

#define CG 128
#define CN 64
#define CS 64
#define KK 27
#define EPS 1e-5f

#define MAX_NG 60000
#define MAX_NX 200000

// -------- scratch (device globals) --------
__device__ __half d_fg[MAX_NG * CN];
__device__ __half d_fs[MAX_NG * CN];
__device__ float d_z[MAX_NG];
__device__ float d_att[MAX_NG];
__device__ float d_S[MAX_NX * KK];
__device__ float d_colstats[4 * CN];      // [sum_g, sq_g | sum_s, sq_s]
__device__ float d_zstats[2];

// ---- packed f32x2 helpers (sm_103a FFMA2 via PTX) ----
__device__ __forceinline__ unsigned long long fma2(
    unsigned long long a, unsigned long long b, unsigned long long c) {
    unsigned long long d;
    asm("fma.rn.f32x2 %0, %1, %2, %3;" : "=l"(d) : "l"(a), "l"(b), "l"(c));
    return d;
}
__device__ __forceinline__ unsigned long long dup2(float v) {
    unsigned long long d;
    asm("mov.b64 %0, {%1, %1};" : "=l"(d) : "r"(__float_as_uint(v)));
    return d;
}
union P2 { unsigned long long u; float2 f; };
union W4 { float4 f4; unsigned long long u[2]; };
union H4 { uint4 u; __half2 h[4]; };

// -------- zero scratch --------
__global__ void zero_kernel(int nS) {
    int i = blockIdx.x * blockDim.x + threadIdx.x;
    int stride = gridDim.x * blockDim.x;
    float4* S4 = (float4*)d_S;
    const float4 z4 = make_float4(0.f, 0.f, 0.f, 0.f);
    int nS4 = nS >> 2;
    for (int e = i; e < nS4; e += stride) S4[e] = z4;
    for (int e = (nS4 << 2) + i; e < nS; e += stride) d_S[e] = 0.f;
    if (i < 4 * CN) d_colstats[i] = 0.f;
    if (i < 2) d_zstats[i] = 0.f;
}

// ============ fg = g @ Wg (Ng x 128 @ 128 x 64), FFMA2, fused stats ============
// 256 thr: 128-row tile, thread = 4 rows x 8 cols (4 f32x2 accumulators per row).
__global__ __launch_bounds__(256) void gemm_g_kernel(
    const float* __restrict__ g, const float* __restrict__ Wg, int Ng) {
    __shared__ float Wsm[CG * CN];  // 32 KB, reused for stats reduction
    int t = threadIdx.x;
    for (int i = t; i < CG * CN; i += 256) Wsm[i] = Wg[i];
    __syncthreads();

    const int tr = t >> 3;
    const int c0 = (t & 7) * 8;
    const int r0 = blockIdx.x * 128 + tr * 4;

    unsigned long long acc[4][4];
#pragma unroll
    for (int j = 0; j < 4; j++)
#pragma unroll
        for (int i = 0; i < 4; i++) acc[j][i] = 0ull;

    bool v[4];
    const float4* gp[4];
#pragma unroll
    for (int j = 0; j < 4; j++) {
        v[j] = (r0 + j) < Ng;
        gp[j] = (const float4*)(g + (size_t)(r0 + j) * CG);
    }
    const float4 zero4 = make_float4(0.f, 0.f, 0.f, 0.f);

#pragma unroll 2
    for (int k4 = 0; k4 < CG / 4; k4++) {
        float4 a[4];
#pragma unroll
        for (int j = 0; j < 4; j++) a[j] = v[j] ? __ldg(&gp[j][k4]) : zero4;
#pragma unroll
        for (int kk = 0; kk < 4; kk++) {
            int k = k4 * 4 + kk;
            W4 w0, w1;
            w0.f4 = *(const float4*)&Wsm[k * CN + c0];
            w1.f4 = *(const float4*)&Wsm[k * CN + c0 + 4];
#pragma unroll
            for (int j = 0; j < 4; j++) {
                unsigned long long av = dup2((&a[j].x)[kk]);
                acc[j][0] = fma2(av, w0.u[0], acc[j][0]);
                acc[j][1] = fma2(av, w0.u[1], acc[j][1]);
                acc[j][2] = fma2(av, w1.u[0], acc[j][2]);
                acc[j][3] = fma2(av, w1.u[1], acc[j][3]);
            }
        }
    }

    // unpack, store fp16, accumulate stats
    float csum[8], csq[8];
#pragma unroll
    for (int i = 0; i < 8; i++) { csum[i] = 0.f; csq[i] = 0.f; }
#pragma unroll
    for (int j = 0; j < 4; j++) {
        float av[8];
#pragma unroll
        for (int i = 0; i < 4; i++) {
            P2 p; p.u = acc[j][i];
            av[2 * i] = p.f.x; av[2 * i + 1] = p.f.y;
        }
        if (r0 + j < Ng) {
            H4 st;
#pragma unroll
            for (int i = 0; i < 4; i++)
                st.h[i] = __floats2half2_rn(av[2 * i], av[2 * i + 1]);
            *(uint4*)&d_fg[(size_t)(r0 + j) * CN + c0] = st.u;
        }
#pragma unroll
        for (int i = 0; i < 8; i++) { csum[i] += av[i]; csq[i] += av[i] * av[i]; }
    }

    __syncthreads();
    float* s_sum = Wsm;
    float* s_sq  = Wsm + 2048;
#pragma unroll
    for (int i = 0; i < 8; i++) {
        s_sum[tr * 64 + c0 + i] = csum[i];
        s_sq[tr * 64 + c0 + i]  = csq[i];
    }
    __syncthreads();
    int col = t & 63, seg = t >> 6;
    float v1 = 0.f, v2 = 0.f;
#pragma unroll
    for (int r = 0; r < 8; r++) {
        v1 += s_sum[(seg * 8 + r) * 64 + col];
        v2 += s_sq[(seg * 8 + r) * 64 + col];
    }
    __syncthreads();
    s_sum[seg * 64 + col] = v1;
    s_sq[seg * 64 + col]  = v2;
    __syncthreads();
    if (t < 64) {
        float a = s_sum[t] + s_sum[64 + t] + s_sum[128 + t] + s_sum[192 + t];
        float b = s_sq[t]  + s_sq[64 + t]  + s_sq[128 + t]  + s_sq[192 + t];
        atomicAdd(&d_colstats[t], a);
        atomicAdd(&d_colstats[64 + t], b);
    }
}

// ============ fs = x[down_idx] @ Ws (Ng x 64 @ 64 x 64), FFMA2, fused stats ============
__global__ __launch_bounds__(256) void gemm_s_kernel(
    const float* __restrict__ x, const int* __restrict__ down_idx,
    const float* __restrict__ Ws, int Ng) {
    __shared__ float Wsm[CS * CN];  // 16 KB
    __shared__ float s_red[4096];   // 16 KB
    __shared__ int ds[128];
    int t = threadIdx.x;
    for (int i = t; i < CS * CN; i += 256) Wsm[i] = Ws[i];
    int rbase = blockIdx.x * 128;
    if (t < 128) ds[t] = (rbase + t < Ng) ? down_idx[rbase + t] : 0;
    __syncthreads();

    const int tr = t >> 3;
    const int c0 = (t & 7) * 8;
    const int r0 = rbase + tr * 4;

    unsigned long long acc[4][4];
#pragma unroll
    for (int j = 0; j < 4; j++)
#pragma unroll
        for (int i = 0; i < 4; i++) acc[j][i] = 0ull;

    bool v[4];
    const float4* xp[4];
#pragma unroll
    for (int j = 0; j < 4; j++) {
        v[j] = (r0 + j) < Ng;
        xp[j] = (const float4*)(x + (size_t)ds[tr * 4 + j] * CS);
    }
    const float4 zero4 = make_float4(0.f, 0.f, 0.f, 0.f);

#pragma unroll 2
    for (int k4 = 0; k4 < CS / 4; k4++) {
        float4 a[4];
#pragma unroll
        for (int j = 0; j < 4; j++) a[j] = v[j] ? __ldg(&xp[j][k4]) : zero4;
#pragma unroll
        for (int kk = 0; kk < 4; kk++) {
            int k = k4 * 4 + kk;
            W4 w0, w1;
            w0.f4 = *(const float4*)&Wsm[k * CN + c0];
            w1.f4 = *(const float4*)&Wsm[k * CN + c0 + 4];
#pragma unroll
            for (int j = 0; j < 4; j++) {
                unsigned long long av = dup2((&a[j].x)[kk]);
                acc[j][0] = fma2(av, w0.u[0], acc[j][0]);
                acc[j][1] = fma2(av, w0.u[1], acc[j][1]);
                acc[j][2] = fma2(av, w1.u[0], acc[j][2]);
                acc[j][3] = fma2(av, w1.u[1], acc[j][3]);
            }
        }
    }

    float csum[8], csq[8];
#pragma unroll
    for (int i = 0; i < 8; i++) { csum[i] = 0.f; csq[i] = 0.f; }
#pragma unroll
    for (int j = 0; j < 4; j++) {
        float av[8];
#pragma unroll
        for (int i = 0; i < 4; i++) {
            P2 p; p.u = acc[j][i];
            av[2 * i] = p.f.x; av[2 * i + 1] = p.f.y;
        }
        if (r0 + j < Ng) {
            H4 st;
#pragma unroll
            for (int i = 0; i < 4; i++)
                st.h[i] = __floats2half2_rn(av[2 * i], av[2 * i + 1]);
            *(uint4*)&d_fs[(size_t)(r0 + j) * CN + c0] = st.u;
        }
#pragma unroll
        for (int i = 0; i < 8; i++) { csum[i] += av[i]; csq[i] += av[i] * av[i]; }
    }

    float* s_sum = s_red;
    float* s_sq  = s_red + 2048;
#pragma unroll
    for (int i = 0; i < 8; i++) {
        s_sum[tr * 64 + c0 + i] = csum[i];
        s_sq[tr * 64 + c0 + i]  = csq[i];
    }
    __syncthreads();
    int col = t & 63, seg = t >> 6;
    float v1 = 0.f, v2 = 0.f;
#pragma unroll
    for (int r = 0; r < 8; r++) {
        v1 += s_sum[(seg * 8 + r) * 64 + col];
        v2 += s_sq[(seg * 8 + r) * 64 + col];
    }
    __syncthreads();
    s_sum[seg * 64 + col] = v1;
    s_sq[seg * 64 + col]  = v2;
    __syncthreads();
    if (t < 64) {
        float a = s_sum[t] + s_sum[64 + t] + s_sum[128 + t] + s_sum[192 + t];
        float b = s_sq[t]  + s_sq[64 + t]  + s_sq[128 + t]  + s_sq[192 + t];
        atomicAdd(&d_colstats[128 + t], a);
        atomicAdd(&d_colstats[192 + t], b);
    }
}

// -------- fuse: z = (relu(bn_g(fg)) + relu(bn_s(fs))) . Wc; z-stats --------
// Warp handles 4 rows: 8 lanes/row, each lane 8 cols via one uint4 (8 halves).
__global__ __launch_bounds__(256) void fuse_kernel(
    const float* __restrict__ Wc,
    const float* __restrict__ gg, const float* __restrict__ bg,
    const float* __restrict__ gs, const float* __restrict__ bs, int Ng) {
    __shared__ float wc[CN], sgn[CN], bgn[CN], ssn[CN], bsn[CN];
    __shared__ float zs[8][2];
    int t = threadIdx.x;
    if (t < 128) {
        const int c = t & 63;
        const int br = t >> 6;
        float sum = d_colstats[br * 128 + c];
        float sq  = d_colstats[br * 128 + 64 + c];
        const float inv = 1.f / (float)Ng;
        float mu = sum * inv;
        float var = sq * inv - mu * mu;
        float gam = br ? __ldg(&gs[c]) : __ldg(&gg[c]);
        float bet = br ? __ldg(&bs[c]) : __ldg(&bg[c]);
        float sc = gam * rsqrtf(var + EPS);
        if (br == 0) { sgn[c] = sc; bgn[c] = bet - mu * sc; wc[c] = __ldg(&Wc[c]); }
        else         { ssn[c] = sc; bsn[c] = bet - mu * sc; }
    }
    __syncthreads();

    const int wid = t >> 5, lane = t & 31;
    const int rgrp = lane >> 3;           // 0..3 : row within quad
    const int cg = (lane & 7) * 8;        // 8-column group
    float bsum = 0.f, bsq = 0.f;

    for (int rowb = (blockIdx.x * 8 + wid) * 4; rowb < Ng; rowb += gridDim.x * 32) {
        const int row = rowb + rgrp;
        float part = 0.f;
        if (row < Ng) {
            H4 fgv, fsv;
            fgv.u = *(const uint4*)&d_fg[(size_t)row * CN + cg];
            fsv.u = *(const uint4*)&d_fs[(size_t)row * CN + cg];
#pragma unroll
            for (int i = 0; i < 4; i++) {
                float2 f2 = __half22float2(fgv.h[i]);
                float2 s2 = __half22float2(fsv.h[i]);
                int c = cg + 2 * i;
                float h0 = fmaxf(f2.x * sgn[c] + bgn[c], 0.f) + fmaxf(s2.x * ssn[c] + bsn[c], 0.f);
                float h1 = fmaxf(f2.y * sgn[c + 1] + bgn[c + 1], 0.f) + fmaxf(s2.y * ssn[c + 1] + bsn[c + 1], 0.f);
                part += h0 * wc[c] + h1 * wc[c + 1];
            }
        }
#pragma unroll
        for (int o = 4; o > 0; o >>= 1) part += __shfl_xor_sync(0xffffffffu, part, o);
        if ((lane & 7) == 0 && row < Ng) {
            d_z[row] = part;
            bsum += part;
            bsq += part * part;
        }
    }
    bsum += __shfl_down_sync(0xffffffffu, bsum, 16);
    bsum += __shfl_down_sync(0xffffffffu, bsum, 8);
    bsq  += __shfl_down_sync(0xffffffffu, bsq, 16);
    bsq  += __shfl_down_sync(0xffffffffu, bsq, 8);
    if (lane == 0) { zs[wid][0] = bsum; zs[wid][1] = bsq; }
    __syncthreads();
    if (t == 0) {
        float a = 0.f, q = 0.f;
#pragma unroll
        for (int w = 0; w < 8; w++) { a += zs[w][0]; q += zs[w][1]; }
        atomicAdd(&d_zstats[0], a);
        atomicAdd(&d_zstats[1], q);
    }
}

// -------- att = sigmoid(bn(z)) --------
__global__ void att_kernel(const float* __restrict__ gamma_c,
                           const float* __restrict__ beta_c, int Ng) {
    int i = blockIdx.x * blockDim.x + threadIdx.x;
    if (i >= Ng) return;
    const float inv = 1.f / (float)Ng;
    float mu = d_zstats[0] * inv;
    float var = d_zstats[1] * inv - mu * mu;
    float rs = rsqrtf(var + EPS);
    float zz = (d_z[i] - mu) * rs * gamma_c[0] + beta_c[0];
    d_att[i] = 1.f / (1.f + expf(-zz));
}

// -------- scatter scalar att into S[Nx][27] --------
__global__ void scatter_kernel(const int* __restrict__ pin,
                               const int* __restrict__ pout, int P) {
    int i = blockIdx.x * blockDim.x + threadIdx.x;
    if (i >= P) return;
    int k = blockIdx.y;
    int e = k * P + i;
    float a = d_att[__ldg(&pin[e])];
    atomicAdd(&d_S[(size_t)__ldg(&pout[e]) * KK + k], a);
}

// -------- out = x * (S @ W_inv + b_inv) --------
__global__ __launch_bounds__(256) void output_kernel(
    const float* __restrict__ x, const float* __restrict__ Winv,
    const float* __restrict__ binv, float* __restrict__ out, int Nx) {
    __shared__ float w[KK][CN];
    __shared__ float bb[CN];
    int t = threadIdx.x;
    for (int i = t; i < KK * CN; i += 256) w[i / CN][i % CN] = Winv[i];
    if (t < CN) bb[t] = binv[t];
    __syncthreads();
    int wid = t >> 5, l = t & 31;
    for (int row = blockIdx.x * 8 + wid; row < Nx; row += gridDim.x * 8) {
        float sval = (l < KK) ? d_S[(size_t)row * KK + l] : 0.f;
        const int c = 2 * l;
        float a0 = bb[c], a1 = bb[c + 1];
#pragma unroll
        for (int k = 0; k < KK; k++) {
            float sk = __shfl_sync(0xffffffffu, sval, k);
            float2 wk = *(const float2*)&w[k][c];
            a0 = fmaf(sk, wk.x, a0);
            a1 = fmaf(sk, wk.y, a1);
        }
        float2 xv = *(const float2*)&x[(size_t)row * CS + c];
        float2 o;
        o.x = xv.x * a0;
        o.y = xv.y * a1;
        *(float2*)&out[(size_t)row * CS + c] = o;
    }
}

extern "C" void kernel_launch(void* const* d_in, const int* in_sizes, int n_in,
                              void* d_out, int out_size) {
    const float* g        = (const float*)d_in[0];
    const float* x        = (const float*)d_in[1];
    const int*   down_idx = (const int*)d_in[2];
    const int*   pairs_in = (const int*)d_in[3];
    const int*   pairs_out= (const int*)d_in[4];
    const float* Wg       = (const float*)d_in[5];
    const float* Ws       = (const float*)d_in[6];
    const float* Wc       = (const float*)d_in[7];
    const float* W_inv    = (const float*)d_in[8];
    const float* b_inv    = (const float*)d_in[9];
    const float* gamma_g  = (const float*)d_in[10];
    const float* beta_g   = (const float*)d_in[11];
    const float* gamma_s  = (const float*)d_in[12];
    const float* beta_s   = (const float*)d_in[13];
    const float* gamma_c  = (const float*)d_in[14];
    const float* beta_c   = (const float*)d_in[15];

    int Ng = in_sizes[0] / CG;
    int Nx = in_sizes[1] / CS;
    int KP = in_sizes[3];
    int P  = KP / KK;

    zero_kernel<<<2048, 256>>>(Nx * KK);
    gemm_g_kernel<<<(Ng + 127) / 128, 256>>>(g, Wg, Ng);
    gemm_s_kernel<<<(Ng + 127) / 128, 256>>>(x, down_idx, Ws, Ng);
    fuse_kernel<<<(Ng + 31) / 32, 256>>>(Wc, gamma_g, beta_g, gamma_s, beta_s, Ng);
    att_kernel<<<(Ng + 255) / 256, 256>>>(gamma_c, beta_c, Ng);
    dim3 sgrid((P + 255) / 256, KK);
    scatter_kernel<<<sgrid, 256>>>(pairs_in, pairs_out, P);
    output_kernel<<<(Nx + 7) / 8, 256>>>(x, W_inv, b_inv, (float*)d_out, Nx);
}

// round 5
// speedup vs baseline: 1.6825x; 1.2326x over previous
#include <cuda_runtime.h>
#include <cuda_fp16.h>
#include <math.h>

#define CG 128
#define CN 64
#define CS 64
#define KK 27
#define EPS 1e-5f

#define MAX_NG 60000
#define MAX_NX 200000

// -------- scratch (device globals) --------
__device__ __half d_fg[MAX_NG * CN];
__device__ __half d_fs[MAX_NG * CN];
__device__ float d_z[MAX_NG];
__device__ float d_att[MAX_NG];
__device__ float d_S[MAX_NX * KK];
__device__ float d_colstats[4 * CN];
__device__ float d_zstats[2];

// ---- packed f32x2 helpers (sm_103a FFMA2 via PTX) ----
__device__ __forceinline__ unsigned long long fma2(
    unsigned long long a, unsigned long long b, unsigned long long c) {
    unsigned long long d;
    asm("fma.rn.f32x2 %0, %1, %2, %3;" : "=l"(d) : "l"(a), "l"(b), "l"(c));
    return d;
}
__device__ __forceinline__ unsigned long long dup2(float v) {
    unsigned long long d;
    asm("mov.b64 %0, {%1, %1};" : "=l"(d) : "r"(__float_as_uint(v)));
    return d;
}
union P2 { unsigned long long u; float2 f; };
union W4 { float4 f4; unsigned long long u[2]; };
union H4 { uint4 u; __half2 h[4]; };

// -------- zero scratch --------
__global__ void zero_kernel(int nS) {
    int i = blockIdx.x * blockDim.x + threadIdx.x;
    int stride = gridDim.x * blockDim.x;
    float4* S4 = (float4*)d_S;
    const float4 z4 = make_float4(0.f, 0.f, 0.f, 0.f);
    int nS4 = nS >> 2;
    for (int e = i; e < nS4; e += stride) S4[e] = z4;
    for (int e = (nS4 << 2) + i; e < nS; e += stride) d_S[e] = 0.f;
    if (i < 4 * CN) d_colstats[i] = 0.f;
    if (i < 2) d_zstats[i] = 0.f;
}

// ============ fg = g @ Wg (Ng x 128 @ 128 x 64), FFMA2, fused stats ============
__global__ __launch_bounds__(256) void gemm_g_kernel(
    const float* __restrict__ g, const float* __restrict__ Wg, int Ng) {
    __shared__ float Wsm[CG * CN];
    int t = threadIdx.x;
    for (int i = t; i < CG * CN; i += 256) Wsm[i] = Wg[i];
    __syncthreads();

    const int tr = t >> 3;
    const int c0 = (t & 7) * 8;
    const int r0 = blockIdx.x * 128 + tr * 4;

    unsigned long long acc[4][4];
#pragma unroll
    for (int j = 0; j < 4; j++)
#pragma unroll
        for (int i = 0; i < 4; i++) acc[j][i] = 0ull;

    bool v[4];
    const float4* gp[4];
#pragma unroll
    for (int j = 0; j < 4; j++) {
        v[j] = (r0 + j) < Ng;
        gp[j] = (const float4*)(g + (size_t)(r0 + j) * CG);
    }
    const float4 zero4 = make_float4(0.f, 0.f, 0.f, 0.f);

#pragma unroll 2
    for (int k4 = 0; k4 < CG / 4; k4++) {
        float4 a[4];
#pragma unroll
        for (int j = 0; j < 4; j++) a[j] = v[j] ? __ldg(&gp[j][k4]) : zero4;
#pragma unroll
        for (int kk = 0; kk < 4; kk++) {
            int k = k4 * 4 + kk;
            W4 w0, w1;
            w0.f4 = *(const float4*)&Wsm[k * CN + c0];
            w1.f4 = *(const float4*)&Wsm[k * CN + c0 + 4];
#pragma unroll
            for (int j = 0; j < 4; j++) {
                unsigned long long av = dup2((&a[j].x)[kk]);
                acc[j][0] = fma2(av, w0.u[0], acc[j][0]);
                acc[j][1] = fma2(av, w0.u[1], acc[j][1]);
                acc[j][2] = fma2(av, w1.u[0], acc[j][2]);
                acc[j][3] = fma2(av, w1.u[1], acc[j][3]);
            }
        }
    }

    float csum[8], csq[8];
#pragma unroll
    for (int i = 0; i < 8; i++) { csum[i] = 0.f; csq[i] = 0.f; }
#pragma unroll
    for (int j = 0; j < 4; j++) {
        float av[8];
#pragma unroll
        for (int i = 0; i < 4; i++) {
            P2 p; p.u = acc[j][i];
            av[2 * i] = p.f.x; av[2 * i + 1] = p.f.y;
        }
        if (r0 + j < Ng) {
            H4 st;
#pragma unroll
            for (int i = 0; i < 4; i++)
                st.h[i] = __floats2half2_rn(av[2 * i], av[2 * i + 1]);
            *(uint4*)&d_fg[(size_t)(r0 + j) * CN + c0] = st.u;
        }
#pragma unroll
        for (int i = 0; i < 8; i++) { csum[i] += av[i]; csq[i] += av[i] * av[i]; }
    }

    __syncthreads();
    float* s_sum = Wsm;
    float* s_sq  = Wsm + 2048;
#pragma unroll
    for (int i = 0; i < 8; i++) {
        s_sum[tr * 64 + c0 + i] = csum[i];
        s_sq[tr * 64 + c0 + i]  = csq[i];
    }
    __syncthreads();
    int col = t & 63, seg = t >> 6;
    float v1 = 0.f, v2 = 0.f;
#pragma unroll
    for (int r = 0; r < 8; r++) {
        v1 += s_sum[(seg * 8 + r) * 64 + col];
        v2 += s_sq[(seg * 8 + r) * 64 + col];
    }
    __syncthreads();
    s_sum[seg * 64 + col] = v1;
    s_sq[seg * 64 + col]  = v2;
    __syncthreads();
    if (t < 64) {
        float a = s_sum[t] + s_sum[64 + t] + s_sum[128 + t] + s_sum[192 + t];
        float b = s_sq[t]  + s_sq[64 + t]  + s_sq[128 + t]  + s_sq[192 + t];
        atomicAdd(&d_colstats[t], a);
        atomicAdd(&d_colstats[64 + t], b);
    }
}

// ============ fs = x[down_idx] @ Ws (Ng x 64 @ 64 x 64), FFMA2, fused stats ============
__global__ __launch_bounds__(256) void gemm_s_kernel(
    const float* __restrict__ x, const int* __restrict__ down_idx,
    const float* __restrict__ Ws, int Ng) {
    __shared__ float Wsm[CS * CN];
    __shared__ float s_red[4096];
    __shared__ int ds[128];
    int t = threadIdx.x;
    for (int i = t; i < CS * CN; i += 256) Wsm[i] = Ws[i];
    int rbase = blockIdx.x * 128;
    if (t < 128) ds[t] = (rbase + t < Ng) ? down_idx[rbase + t] : 0;
    __syncthreads();

    const int tr = t >> 3;
    const int c0 = (t & 7) * 8;
    const int r0 = rbase + tr * 4;

    unsigned long long acc[4][4];
#pragma unroll
    for (int j = 0; j < 4; j++)
#pragma unroll
        for (int i = 0; i < 4; i++) acc[j][i] = 0ull;

    bool v[4];
    const float4* xp[4];
#pragma unroll
    for (int j = 0; j < 4; j++) {
        v[j] = (r0 + j) < Ng;
        xp[j] = (const float4*)(x + (size_t)ds[tr * 4 + j] * CS);
    }
    const float4 zero4 = make_float4(0.f, 0.f, 0.f, 0.f);

#pragma unroll 2
    for (int k4 = 0; k4 < CS / 4; k4++) {
        float4 a[4];
#pragma unroll
        for (int j = 0; j < 4; j++) a[j] = v[j] ? __ldg(&xp[j][k4]) : zero4;
#pragma unroll
        for (int kk = 0; kk < 4; kk++) {
            int k = k4 * 4 + kk;
            W4 w0, w1;
            w0.f4 = *(const float4*)&Wsm[k * CN + c0];
            w1.f4 = *(const float4*)&Wsm[k * CN + c0 + 4];
#pragma unroll
            for (int j = 0; j < 4; j++) {
                unsigned long long av = dup2((&a[j].x)[kk]);
                acc[j][0] = fma2(av, w0.u[0], acc[j][0]);
                acc[j][1] = fma2(av, w0.u[1], acc[j][1]);
                acc[j][2] = fma2(av, w1.u[0], acc[j][2]);
                acc[j][3] = fma2(av, w1.u[1], acc[j][3]);
            }
        }
    }

    float csum[8], csq[8];
#pragma unroll
    for (int i = 0; i < 8; i++) { csum[i] = 0.f; csq[i] = 0.f; }
#pragma unroll
    for (int j = 0; j < 4; j++) {
        float av[8];
#pragma unroll
        for (int i = 0; i < 4; i++) {
            P2 p; p.u = acc[j][i];
            av[2 * i] = p.f.x; av[2 * i + 1] = p.f.y;
        }
        if (r0 + j < Ng) {
            H4 st;
#pragma unroll
            for (int i = 0; i < 4; i++)
                st.h[i] = __floats2half2_rn(av[2 * i], av[2 * i + 1]);
            *(uint4*)&d_fs[(size_t)(r0 + j) * CN + c0] = st.u;
        }
#pragma unroll
        for (int i = 0; i < 8; i++) { csum[i] += av[i]; csq[i] += av[i] * av[i]; }
    }

    float* s_sum = s_red;
    float* s_sq  = s_red + 2048;
#pragma unroll
    for (int i = 0; i < 8; i++) {
        s_sum[tr * 64 + c0 + i] = csum[i];
        s_sq[tr * 64 + c0 + i]  = csq[i];
    }
    __syncthreads();
    int col = t & 63, seg = t >> 6;
    float v1 = 0.f, v2 = 0.f;
#pragma unroll
    for (int r = 0; r < 8; r++) {
        v1 += s_sum[(seg * 8 + r) * 64 + col];
        v2 += s_sq[(seg * 8 + r) * 64 + col];
    }
    __syncthreads();
    s_sum[seg * 64 + col] = v1;
    s_sq[seg * 64 + col]  = v2;
    __syncthreads();
    if (t < 64) {
        float a = s_sum[t] + s_sum[64 + t] + s_sum[128 + t] + s_sum[192 + t];
        float b = s_sq[t]  + s_sq[64 + t]  + s_sq[128 + t]  + s_sq[192 + t];
        atomicAdd(&d_colstats[128 + t], a);
        atomicAdd(&d_colstats[192 + t], b);
    }
}

// -------- fuse: z = (relu(bn_g(fg)) + relu(bn_s(fs))) . Wc; z-stats --------
// Warp handles 8 rows/pass (2 quads), 4 uint4 loads in flight -> high MLP.
__global__ __launch_bounds__(256) void fuse_kernel(
    const float* __restrict__ Wc,
    const float* __restrict__ gg, const float* __restrict__ bg,
    const float* __restrict__ gs, const float* __restrict__ bs, int Ng) {
    __shared__ float wc[CN], sgn[CN], bgn[CN], ssn[CN], bsn[CN];
    __shared__ float zs[8][2];
    int t = threadIdx.x;
    if (t < 128) {
        const int c = t & 63;
        const int br = t >> 6;
        float sum = d_colstats[br * 128 + c];
        float sq  = d_colstats[br * 128 + 64 + c];
        const float inv = 1.f / (float)Ng;
        float mu = sum * inv;
        float var = sq * inv - mu * mu;
        float gam = br ? __ldg(&gs[c]) : __ldg(&gg[c]);
        float bet = br ? __ldg(&bs[c]) : __ldg(&bg[c]);
        float sc = gam * rsqrtf(var + EPS);
        if (br == 0) { sgn[c] = sc; bgn[c] = bet - mu * sc; wc[c] = __ldg(&Wc[c]); }
        else         { ssn[c] = sc; bsn[c] = bet - mu * sc; }
    }
    __syncthreads();

    const int wid = t >> 5, lane = t & 31;
    const int rgrp = lane >> 3;           // 0..3
    const int cg = (lane & 7) * 8;        // 8-col group
    float bsum = 0.f, bsq = 0.f;

    for (int rowb = (blockIdx.x * 8 + wid) * 8; rowb < Ng; rowb += gridDim.x * 64) {
        int row[2] = { rowb + rgrp, rowb + 4 + rgrp };
        H4 fgv[2], fsv[2];
#pragma unroll
        for (int q = 0; q < 2; q++) {
            if (row[q] < Ng) {
                fgv[q].u = *(const uint4*)&d_fg[(size_t)row[q] * CN + cg];
                fsv[q].u = *(const uint4*)&d_fs[(size_t)row[q] * CN + cg];
            }
        }
#pragma unroll
        for (int q = 0; q < 2; q++) {
            float part = 0.f;
            if (row[q] < Ng) {
#pragma unroll
                for (int i = 0; i < 4; i++) {
                    float2 f2 = __half22float2(fgv[q].h[i]);
                    float2 s2 = __half22float2(fsv[q].h[i]);
                    int c = cg + 2 * i;
                    float h0 = fmaxf(f2.x * sgn[c] + bgn[c], 0.f) + fmaxf(s2.x * ssn[c] + bsn[c], 0.f);
                    float h1 = fmaxf(f2.y * sgn[c + 1] + bgn[c + 1], 0.f) + fmaxf(s2.y * ssn[c + 1] + bsn[c + 1], 0.f);
                    part += h0 * wc[c] + h1 * wc[c + 1];
                }
            }
#pragma unroll
            for (int o = 4; o > 0; o >>= 1) part += __shfl_xor_sync(0xffffffffu, part, o);
            if ((lane & 7) == 0 && row[q] < Ng) {
                d_z[row[q]] = part;
                bsum += part;
                bsq += part * part;
            }
        }
    }
    bsum += __shfl_down_sync(0xffffffffu, bsum, 16);
    bsum += __shfl_down_sync(0xffffffffu, bsum, 8);
    bsq  += __shfl_down_sync(0xffffffffu, bsq, 16);
    bsq  += __shfl_down_sync(0xffffffffu, bsq, 8);
    if (lane == 0) { zs[wid][0] = bsum; zs[wid][1] = bsq; }
    __syncthreads();
    if (t == 0) {
        float a = 0.f, q = 0.f;
#pragma unroll
        for (int w = 0; w < 8; w++) { a += zs[w][0]; q += zs[w][1]; }
        atomicAdd(&d_zstats[0], a);
        atomicAdd(&d_zstats[1], q);
    }
}

// -------- att = sigmoid(bn(z)) --------
__global__ void att_kernel(const float* __restrict__ gamma_c,
                           const float* __restrict__ beta_c, int Ng) {
    int i = blockIdx.x * blockDim.x + threadIdx.x;
    if (i >= Ng) return;
    const float inv = 1.f / (float)Ng;
    float mu = d_zstats[0] * inv;
    float var = d_zstats[1] * inv - mu * mu;
    float rs = rsqrtf(var + EPS);
    float zz = (d_z[i] - mu) * rs * gamma_c[0] + beta_c[0];
    d_att[i] = 1.f / (1.f + expf(-zz));
}

// -------- scatter: 4 pairs per thread (uint4 loads, 4 gathers in flight) --------
__global__ void scatter_kernel(const int* __restrict__ pin,
                               const int* __restrict__ pout, int P) {
    int i4 = (blockIdx.x * blockDim.x + threadIdx.x) * 4;
    int k = blockIdx.y;
    if (i4 + 3 < P) {
        uint4 pi = *(const uint4*)&pin[(size_t)k * P + i4];
        uint4 po = *(const uint4*)&pout[(size_t)k * P + i4];
        float a0 = __ldg(&d_att[pi.x]);
        float a1 = __ldg(&d_att[pi.y]);
        float a2 = __ldg(&d_att[pi.z]);
        float a3 = __ldg(&d_att[pi.w]);
        atomicAdd(&d_S[(size_t)po.x * KK + k], a0);
        atomicAdd(&d_S[(size_t)po.y * KK + k], a1);
        atomicAdd(&d_S[(size_t)po.z * KK + k], a2);
        atomicAdd(&d_S[(size_t)po.w * KK + k], a3);
    } else {
        for (int i = i4; i < P; i++) {
            float a = __ldg(&d_att[__ldg(&pin[(size_t)k * P + i])]);
            atomicAdd(&d_S[(size_t)__ldg(&pout[(size_t)k * P + i]) * KK + k], a);
        }
    }
}

// -------- out = x * (S @ W_inv + b_inv); warp = 8 rows/pass, MLP 16 --------
__global__ __launch_bounds__(256) void output_kernel(
    const float* __restrict__ x, const float* __restrict__ Winv,
    const float* __restrict__ binv, float* __restrict__ out, int Nx) {
    __shared__ float w[KK * CN];
    __shared__ float bb[CN];
    int t = threadIdx.x;
    for (int i = t; i < KK * CN; i += 256) w[i] = Winv[i];
    if (t < CN) bb[t] = binv[t];
    __syncthreads();
    const int wid = t >> 5, lane = t & 31;
    const int c = 2 * lane;
    const int r0 = (blockIdx.x * 8 + wid) * 8;
    if (r0 >= Nx) return;

    // issue all independent loads first: 8 S rows + 8 x row-fragments
    float sv[8];
    float2 xv[8];
#pragma unroll
    for (int j = 0; j < 8; j++)
        sv[j] = (lane < KK && r0 + j < Nx) ? __ldg(&d_S[(size_t)(r0 + j) * KK + lane]) : 0.f;
#pragma unroll
    for (int j = 0; j < 8; j++)
        xv[j] = (r0 + j < Nx) ? *(const float2*)&x[(size_t)(r0 + j) * CS + c]
                              : make_float2(0.f, 0.f);

    float2 acc[8];
    const float b0 = bb[c], b1 = bb[c + 1];
#pragma unroll
    for (int j = 0; j < 8; j++) { acc[j].x = b0; acc[j].y = b1; }

#pragma unroll
    for (int k = 0; k < KK; k++) {
        float2 wk = *(const float2*)&w[k * CN + c];
#pragma unroll
        for (int j = 0; j < 8; j++) {
            float sk = __shfl_sync(0xffffffffu, sv[j], k);
            acc[j].x = fmaf(sk, wk.x, acc[j].x);
            acc[j].y = fmaf(sk, wk.y, acc[j].y);
        }
    }
#pragma unroll
    for (int j = 0; j < 8; j++) {
        if (r0 + j < Nx) {
            float2 o;
            o.x = xv[j].x * acc[j].x;
            o.y = xv[j].y * acc[j].y;
            *(float2*)&out[(size_t)(r0 + j) * CS + c] = o;
        }
    }
}

extern "C" void kernel_launch(void* const* d_in, const int* in_sizes, int n_in,
                              void* d_out, int out_size) {
    const float* g        = (const float*)d_in[0];
    const float* x        = (const float*)d_in[1];
    const int*   down_idx = (const int*)d_in[2];
    const int*   pairs_in = (const int*)d_in[3];
    const int*   pairs_out= (const int*)d_in[4];
    const float* Wg       = (const float*)d_in[5];
    const float* Ws       = (const float*)d_in[6];
    const float* Wc       = (const float*)d_in[7];
    const float* W_inv    = (const float*)d_in[8];
    const float* b_inv    = (const float*)d_in[9];
    const float* gamma_g  = (const float*)d_in[10];
    const float* beta_g   = (const float*)d_in[11];
    const float* gamma_s  = (const float*)d_in[12];
    const float* beta_s   = (const float*)d_in[13];
    const float* gamma_c  = (const float*)d_in[14];
    const float* beta_c   = (const float*)d_in[15];

    int Ng = in_sizes[0] / CG;
    int Nx = in_sizes[1] / CS;
    int KP = in_sizes[3];
    int P  = KP / KK;

    zero_kernel<<<2048, 256>>>(Nx * KK);
    gemm_g_kernel<<<(Ng + 127) / 128, 256>>>(g, Wg, Ng);
    gemm_s_kernel<<<(Ng + 127) / 128, 256>>>(x, down_idx, Ws, Ng);
    fuse_kernel<<<(Ng + 63) / 64, 256>>>(Wc, gamma_g, beta_g, gamma_s, beta_s, Ng);
    att_kernel<<<(Ng + 255) / 256, 256>>>(gamma_c, beta_c, Ng);
    dim3 sgrid(((P + 3) / 4 + 255) / 256, KK);
    scatter_kernel<<<sgrid, 256>>>(pairs_in, pairs_out, P);
    output_kernel<<<(Nx + 63) / 64, 256>>>(x, W_inv, b_inv, (float*)d_out, Nx);
}

// round 6
// speedup vs baseline: 1.8390x; 1.0930x over previous
#include <cuda_runtime.h>
#include <cuda_fp16.h>
#include <math.h>

#define CG 128
#define CN 64
#define CS 64
#define KK 27
#define EPS 1e-5f

#define MAX_NG 60000
#define MAX_NX 200000

// -------- scratch (device globals, zero-initialized at module load) --------
// Invariant: every kernel_launch invocation leaves d_S, d_colstats, d_zstats
// zeroed for the next invocation (output_kernel performs the reset after the
// last read). First invocation relies on static zero-init.
__device__ __half d_fg[MAX_NG * CN];
__device__ __half d_fs[MAX_NG * CN];
__device__ float d_z[MAX_NG];
__device__ float d_S[MAX_NX * KK];
__device__ float d_colstats[4 * CN];
__device__ float d_zstats[2];

// ---- packed f32x2 helpers (sm_103a FFMA2 via PTX) ----
__device__ __forceinline__ unsigned long long fma2(
    unsigned long long a, unsigned long long b, unsigned long long c) {
    unsigned long long d;
    asm("fma.rn.f32x2 %0, %1, %2, %3;" : "=l"(d) : "l"(a), "l"(b), "l"(c));
    return d;
}
__device__ __forceinline__ unsigned long long dup2(float v) {
    unsigned long long d;
    asm("mov.b64 %0, {%1, %1};" : "=l"(d) : "r"(__float_as_uint(v)));
    return d;
}
union P2 { unsigned long long u; float2 f; };
union W4 { float4 f4; unsigned long long u[2]; };
union H4 { uint4 u; __half2 h[4]; };

// ============ fg = g @ Wg (Ng x 128 @ 128 x 64), FFMA2, fused stats ============
__global__ __launch_bounds__(256) void gemm_g_kernel(
    const float* __restrict__ g, const float* __restrict__ Wg, int Ng) {
    __shared__ float Wsm[CG * CN];
    int t = threadIdx.x;
    for (int i = t; i < CG * CN; i += 256) Wsm[i] = Wg[i];
    __syncthreads();

    const int tr = t >> 3;
    const int c0 = (t & 7) * 8;
    const int r0 = blockIdx.x * 128 + tr * 4;

    unsigned long long acc[4][4];
#pragma unroll
    for (int j = 0; j < 4; j++)
#pragma unroll
        for (int i = 0; i < 4; i++) acc[j][i] = 0ull;

    bool v[4];
    const float4* gp[4];
#pragma unroll
    for (int j = 0; j < 4; j++) {
        v[j] = (r0 + j) < Ng;
        gp[j] = (const float4*)(g + (size_t)(r0 + j) * CG);
    }
    const float4 zero4 = make_float4(0.f, 0.f, 0.f, 0.f);

#pragma unroll 2
    for (int k4 = 0; k4 < CG / 4; k4++) {
        float4 a[4];
#pragma unroll
        for (int j = 0; j < 4; j++) a[j] = v[j] ? __ldcs(&gp[j][k4]) : zero4;
#pragma unroll
        for (int kk = 0; kk < 4; kk++) {
            int k = k4 * 4 + kk;
            W4 w0, w1;
            w0.f4 = *(const float4*)&Wsm[k * CN + c0];
            w1.f4 = *(const float4*)&Wsm[k * CN + c0 + 4];
#pragma unroll
            for (int j = 0; j < 4; j++) {
                unsigned long long av = dup2((&a[j].x)[kk]);
                acc[j][0] = fma2(av, w0.u[0], acc[j][0]);
                acc[j][1] = fma2(av, w0.u[1], acc[j][1]);
                acc[j][2] = fma2(av, w1.u[0], acc[j][2]);
                acc[j][3] = fma2(av, w1.u[1], acc[j][3]);
            }
        }
    }

    float csum[8], csq[8];
#pragma unroll
    for (int i = 0; i < 8; i++) { csum[i] = 0.f; csq[i] = 0.f; }
#pragma unroll
    for (int j = 0; j < 4; j++) {
        float av[8];
#pragma unroll
        for (int i = 0; i < 4; i++) {
            P2 p; p.u = acc[j][i];
            av[2 * i] = p.f.x; av[2 * i + 1] = p.f.y;
        }
        if (r0 + j < Ng) {
            H4 st;
#pragma unroll
            for (int i = 0; i < 4; i++)
                st.h[i] = __floats2half2_rn(av[2 * i], av[2 * i + 1]);
            *(uint4*)&d_fg[(size_t)(r0 + j) * CN + c0] = st.u;
        }
#pragma unroll
        for (int i = 0; i < 8; i++) { csum[i] += av[i]; csq[i] += av[i] * av[i]; }
    }

    __syncthreads();
    float* s_sum = Wsm;
    float* s_sq  = Wsm + 2048;
#pragma unroll
    for (int i = 0; i < 8; i++) {
        s_sum[tr * 64 + c0 + i] = csum[i];
        s_sq[tr * 64 + c0 + i]  = csq[i];
    }
    __syncthreads();
    int col = t & 63, seg = t >> 6;
    float v1 = 0.f, v2 = 0.f;
#pragma unroll
    for (int r = 0; r < 8; r++) {
        v1 += s_sum[(seg * 8 + r) * 64 + col];
        v2 += s_sq[(seg * 8 + r) * 64 + col];
    }
    __syncthreads();
    s_sum[seg * 64 + col] = v1;
    s_sq[seg * 64 + col]  = v2;
    __syncthreads();
    if (t < 64) {
        float a = s_sum[t] + s_sum[64 + t] + s_sum[128 + t] + s_sum[192 + t];
        float b = s_sq[t]  + s_sq[64 + t]  + s_sq[128 + t]  + s_sq[192 + t];
        atomicAdd(&d_colstats[t], a);
        atomicAdd(&d_colstats[64 + t], b);
    }
}

// ============ fs = x[down_idx] @ Ws (Ng x 64 @ 64 x 64), FFMA2, fused stats ============
__global__ __launch_bounds__(256) void gemm_s_kernel(
    const float* __restrict__ x, const int* __restrict__ down_idx,
    const float* __restrict__ Ws, int Ng) {
    __shared__ float Wsm[CS * CN];
    __shared__ float s_red[4096];
    __shared__ int ds[128];
    int t = threadIdx.x;
    for (int i = t; i < CS * CN; i += 256) Wsm[i] = Ws[i];
    int rbase = blockIdx.x * 128;
    if (t < 128) ds[t] = (rbase + t < Ng) ? down_idx[rbase + t] : 0;
    __syncthreads();

    const int tr = t >> 3;
    const int c0 = (t & 7) * 8;
    const int r0 = rbase + tr * 4;

    unsigned long long acc[4][4];
#pragma unroll
    for (int j = 0; j < 4; j++)
#pragma unroll
        for (int i = 0; i < 4; i++) acc[j][i] = 0ull;

    bool v[4];
    const float4* xp[4];
#pragma unroll
    for (int j = 0; j < 4; j++) {
        v[j] = (r0 + j) < Ng;
        xp[j] = (const float4*)(x + (size_t)ds[tr * 4 + j] * CS);
    }
    const float4 zero4 = make_float4(0.f, 0.f, 0.f, 0.f);

#pragma unroll 2
    for (int k4 = 0; k4 < CS / 4; k4++) {
        float4 a[4];
#pragma unroll
        for (int j = 0; j < 4; j++) a[j] = v[j] ? __ldg(&xp[j][k4]) : zero4;
#pragma unroll
        for (int kk = 0; kk < 4; kk++) {
            int k = k4 * 4 + kk;
            W4 w0, w1;
            w0.f4 = *(const float4*)&Wsm[k * CN + c0];
            w1.f4 = *(const float4*)&Wsm[k * CN + c0 + 4];
#pragma unroll
            for (int j = 0; j < 4; j++) {
                unsigned long long av = dup2((&a[j].x)[kk]);
                acc[j][0] = fma2(av, w0.u[0], acc[j][0]);
                acc[j][1] = fma2(av, w0.u[1], acc[j][1]);
                acc[j][2] = fma2(av, w1.u[0], acc[j][2]);
                acc[j][3] = fma2(av, w1.u[1], acc[j][3]);
            }
        }
    }

    float csum[8], csq[8];
#pragma unroll
    for (int i = 0; i < 8; i++) { csum[i] = 0.f; csq[i] = 0.f; }
#pragma unroll
    for (int j = 0; j < 4; j++) {
        float av[8];
#pragma unroll
        for (int i = 0; i < 4; i++) {
            P2 p; p.u = acc[j][i];
            av[2 * i] = p.f.x; av[2 * i + 1] = p.f.y;
        }
        if (r0 + j < Ng) {
            H4 st;
#pragma unroll
            for (int i = 0; i < 4; i++)
                st.h[i] = __floats2half2_rn(av[2 * i], av[2 * i + 1]);
            *(uint4*)&d_fs[(size_t)(r0 + j) * CN + c0] = st.u;
        }
#pragma unroll
        for (int i = 0; i < 8; i++) { csum[i] += av[i]; csq[i] += av[i] * av[i]; }
    }

    float* s_sum = s_red;
    float* s_sq  = s_red + 2048;
#pragma unroll
    for (int i = 0; i < 8; i++) {
        s_sum[tr * 64 + c0 + i] = csum[i];
        s_sq[tr * 64 + c0 + i]  = csq[i];
    }
    __syncthreads();
    int col = t & 63, seg = t >> 6;
    float v1 = 0.f, v2 = 0.f;
#pragma unroll
    for (int r = 0; r < 8; r++) {
        v1 += s_sum[(seg * 8 + r) * 64 + col];
        v2 += s_sq[(seg * 8 + r) * 64 + col];
    }
    __syncthreads();
    s_sum[seg * 64 + col] = v1;
    s_sq[seg * 64 + col]  = v2;
    __syncthreads();
    if (t < 64) {
        float a = s_sum[t] + s_sum[64 + t] + s_sum[128 + t] + s_sum[192 + t];
        float b = s_sq[t]  + s_sq[64 + t]  + s_sq[128 + t]  + s_sq[192 + t];
        atomicAdd(&d_colstats[128 + t], a);
        atomicAdd(&d_colstats[192 + t], b);
    }
}

// -------- fuse: z = (relu(bn_g(fg)) + relu(bn_s(fs))) . Wc; z-stats --------
__global__ __launch_bounds__(256) void fuse_kernel(
    const float* __restrict__ Wc,
    const float* __restrict__ gg, const float* __restrict__ bg,
    const float* __restrict__ gs, const float* __restrict__ bs, int Ng) {
    __shared__ float wc[CN], sgn[CN], bgn[CN], ssn[CN], bsn[CN];
    __shared__ float zs[8][2];
    int t = threadIdx.x;
    if (t < 128) {
        const int c = t & 63;
        const int br = t >> 6;
        float sum = d_colstats[br * 128 + c];
        float sq  = d_colstats[br * 128 + 64 + c];
        const float inv = 1.f / (float)Ng;
        float mu = sum * inv;
        float var = sq * inv - mu * mu;
        float gam = br ? __ldg(&gs[c]) : __ldg(&gg[c]);
        float bet = br ? __ldg(&bs[c]) : __ldg(&bg[c]);
        float sc = gam * rsqrtf(var + EPS);
        if (br == 0) { sgn[c] = sc; bgn[c] = bet - mu * sc; wc[c] = __ldg(&Wc[c]); }
        else         { ssn[c] = sc; bsn[c] = bet - mu * sc; }
    }
    __syncthreads();

    const int wid = t >> 5, lane = t & 31;
    const int rgrp = lane >> 3;
    const int cg = (lane & 7) * 8;
    float bsum = 0.f, bsq = 0.f;

    for (int rowb = (blockIdx.x * 8 + wid) * 8; rowb < Ng; rowb += gridDim.x * 64) {
        int row[2] = { rowb + rgrp, rowb + 4 + rgrp };
        H4 fgv[2], fsv[2];
#pragma unroll
        for (int q = 0; q < 2; q++) {
            if (row[q] < Ng) {
                fgv[q].u = __ldcs((const uint4*)&d_fg[(size_t)row[q] * CN + cg]);
                fsv[q].u = __ldcs((const uint4*)&d_fs[(size_t)row[q] * CN + cg]);
            }
        }
#pragma unroll
        for (int q = 0; q < 2; q++) {
            float part = 0.f;
            if (row[q] < Ng) {
#pragma unroll
                for (int i = 0; i < 4; i++) {
                    float2 f2 = __half22float2(fgv[q].h[i]);
                    float2 s2 = __half22float2(fsv[q].h[i]);
                    int c = cg + 2 * i;
                    float h0 = fmaxf(f2.x * sgn[c] + bgn[c], 0.f) + fmaxf(s2.x * ssn[c] + bsn[c], 0.f);
                    float h1 = fmaxf(f2.y * sgn[c + 1] + bgn[c + 1], 0.f) + fmaxf(s2.y * ssn[c + 1] + bsn[c + 1], 0.f);
                    part += h0 * wc[c] + h1 * wc[c + 1];
                }
            }
#pragma unroll
            for (int o = 4; o > 0; o >>= 1) part += __shfl_xor_sync(0xffffffffu, part, o);
            if ((lane & 7) == 0 && row[q] < Ng) {
                d_z[row[q]] = part;
                bsum += part;
                bsq += part * part;
            }
        }
    }
    bsum += __shfl_down_sync(0xffffffffu, bsum, 16);
    bsum += __shfl_down_sync(0xffffffffu, bsum, 8);
    bsq  += __shfl_down_sync(0xffffffffu, bsq, 16);
    bsq  += __shfl_down_sync(0xffffffffu, bsq, 8);
    if (lane == 0) { zs[wid][0] = bsum; zs[wid][1] = bsq; }
    __syncthreads();
    if (t == 0) {
        float a = 0.f, q = 0.f;
#pragma unroll
        for (int w = 0; w < 8; w++) { a += zs[w][0]; q += zs[w][1]; }
        atomicAdd(&d_zstats[0], a);
        atomicAdd(&d_zstats[1], q);
    }
}

// -------- scatter: gather z, inline BN+sigmoid, scatter scalar into S --------
__global__ void scatter_kernel(const int* __restrict__ pin,
                               const int* __restrict__ pout,
                               const float* __restrict__ gamma_c,
                               const float* __restrict__ beta_c,
                               int P, float invNg) {
    // BN(z) fold: zz = z * rs + bc
    float mu = d_zstats[0] * invNg;
    float var = d_zstats[1] * invNg - mu * mu;
    float rs = rsqrtf(var + EPS) * __ldg(&gamma_c[0]);
    float bc = __ldg(&beta_c[0]) - mu * rs;

    int i4 = (blockIdx.x * blockDim.x + threadIdx.x) * 4;
    int k = blockIdx.y;
    if (i4 + 3 < P) {
        uint4 pi = *(const uint4*)&pin[(size_t)k * P + i4];
        uint4 po = *(const uint4*)&pout[(size_t)k * P + i4];
        float z0 = __ldg(&d_z[pi.x]);
        float z1 = __ldg(&d_z[pi.y]);
        float z2 = __ldg(&d_z[pi.z]);
        float z3 = __ldg(&d_z[pi.w]);
        float a0 = 1.f / (1.f + __expf(-(z0 * rs + bc)));
        float a1 = 1.f / (1.f + __expf(-(z1 * rs + bc)));
        float a2 = 1.f / (1.f + __expf(-(z2 * rs + bc)));
        float a3 = 1.f / (1.f + __expf(-(z3 * rs + bc)));
        atomicAdd(&d_S[(size_t)po.x * KK + k], a0);
        atomicAdd(&d_S[(size_t)po.y * KK + k], a1);
        atomicAdd(&d_S[(size_t)po.z * KK + k], a2);
        atomicAdd(&d_S[(size_t)po.w * KK + k], a3);
    } else {
        for (int i = i4; i < P; i++) {
            float z = __ldg(&d_z[__ldg(&pin[(size_t)k * P + i])]);
            float a = 1.f / (1.f + __expf(-(z * rs + bc)));
            atomicAdd(&d_S[(size_t)__ldg(&pout[(size_t)k * P + i]) * KK + k], a);
        }
    }
}

// -------- out = x * (S @ W_inv + b_inv); resets S/colstats/zstats for next run --------
__global__ __launch_bounds__(256) void output_kernel(
    const float* __restrict__ x, const float* __restrict__ Winv,
    const float* __restrict__ binv, float* __restrict__ out, int Nx) {
    __shared__ float w[KK * CN];
    __shared__ float bb[CN];
    int t = threadIdx.x;
    for (int i = t; i < KK * CN; i += 256) w[i] = Winv[i];
    if (t < CN) bb[t] = binv[t];
    if (blockIdx.x == 0) {       // reset accumulators for next invocation
        d_colstats[t] = 0.f;
        if (t < 2) d_zstats[t] = 0.f;
    }
    __syncthreads();
    const int wid = t >> 5, lane = t & 31;
    const int c = 2 * lane;
    const int r0 = (blockIdx.x * 8 + wid) * 8;
    if (r0 >= Nx) return;

    float sv[8];
    float2 xv[8];
#pragma unroll
    for (int j = 0; j < 8; j++)
        sv[j] = (lane < KK && r0 + j < Nx) ? __ldcs(&d_S[(size_t)(r0 + j) * KK + lane]) : 0.f;
#pragma unroll
    for (int j = 0; j < 8; j++)
        xv[j] = (r0 + j < Nx) ? __ldcs((const float2*)&x[(size_t)(r0 + j) * CS + c])
                              : make_float2(0.f, 0.f);
    // reset S for the next invocation (read-before-write in program order)
#pragma unroll
    for (int j = 0; j < 8; j++)
        if (lane < KK && r0 + j < Nx) d_S[(size_t)(r0 + j) * KK + lane] = 0.f;

    float2 acc[8];
    const float b0 = bb[c], b1 = bb[c + 1];
#pragma unroll
    for (int j = 0; j < 8; j++) { acc[j].x = b0; acc[j].y = b1; }

#pragma unroll
    for (int k = 0; k < KK; k++) {
        float2 wk = *(const float2*)&w[k * CN + c];
#pragma unroll
        for (int j = 0; j < 8; j++) {
            float sk = __shfl_sync(0xffffffffu, sv[j], k);
            acc[j].x = fmaf(sk, wk.x, acc[j].x);
            acc[j].y = fmaf(sk, wk.y, acc[j].y);
        }
    }
#pragma unroll
    for (int j = 0; j < 8; j++) {
        if (r0 + j < Nx) {
            float2 o;
            o.x = xv[j].x * acc[j].x;
            o.y = xv[j].y * acc[j].y;
            __stcs((float2*)&out[(size_t)(r0 + j) * CS + c], o);
        }
    }
}

extern "C" void kernel_launch(void* const* d_in, const int* in_sizes, int n_in,
                              void* d_out, int out_size) {
    const float* g        = (const float*)d_in[0];
    const float* x        = (const float*)d_in[1];
    const int*   down_idx = (const int*)d_in[2];
    const int*   pairs_in = (const int*)d_in[3];
    const int*   pairs_out= (const int*)d_in[4];
    const float* Wg       = (const float*)d_in[5];
    const float* Ws       = (const float*)d_in[6];
    const float* Wc       = (const float*)d_in[7];
    const float* W_inv    = (const float*)d_in[8];
    const float* b_inv    = (const float*)d_in[9];
    const float* gamma_g  = (const float*)d_in[10];
    const float* beta_g   = (const float*)d_in[11];
    const float* gamma_s  = (const float*)d_in[12];
    const float* beta_s   = (const float*)d_in[13];
    const float* gamma_c  = (const float*)d_in[14];
    const float* beta_c   = (const float*)d_in[15];

    int Ng = in_sizes[0] / CG;
    int Nx = in_sizes[1] / CS;
    int KP = in_sizes[3];
    int P  = KP / KK;

    gemm_g_kernel<<<(Ng + 127) / 128, 256>>>(g, Wg, Ng);
    gemm_s_kernel<<<(Ng + 127) / 128, 256>>>(x, down_idx, Ws, Ng);
    fuse_kernel<<<(Ng + 63) / 64, 256>>>(Wc, gamma_g, beta_g, gamma_s, beta_s, Ng);
    dim3 sgrid(((P + 3) / 4 + 255) / 256, KK);
    scatter_kernel<<<sgrid, 256>>>(pairs_in, pairs_out, gamma_c, beta_c, P, 1.f / (float)Ng);
    output_kernel<<<(Nx + 63) / 64, 256>>>(x, W_inv, b_inv, (float*)d_out, Nx);
}